// round 9
// baseline (speedup 1.0000x reference)
#include <cuda_runtime.h>

#define NTOK   131072          // H*W*D
#define CCH    96
#define BB     2
#define TN     128             // tokens per tile
#define NTILE  1024            // NTOK/TN
#define NBLK   (BB*NTILE)      // 2048
#define NPART  1248            // 8*144 KV + 96 sumK
#define NCHUNK 4               // token chunks per tile for partials
#define NSEG   32              // reduction segments per batch
#define GRID   148             // persistent blocks
#define RS     132             // smem tile row stride (floats)
#define R4S    (RS/4)
#define WS     100             // weight row stride

__device__ float g_partial[(size_t)NBLK * NCHUNK * NPART];   // ~41 MB
__device__ float g_red1[NSEG * BB * NPART];
__device__ float g_red[BB * NPART];
__device__ float g_ctx[BB * 1152];

typedef unsigned long long ull;

__device__ __forceinline__ ull pack2(float x, float y) {
    ull r; asm("mov.b64 %0, {%1, %2};" : "=l"(r) : "f"(x), "f"(y)); return r;
}
__device__ __forceinline__ void fma2(ull& d, ull a, ull b) {
    asm("fma.rn.f32x2 %0, %1, %2, %0;" : "+l"(d) : "l"(a), "l"(b));
}
__device__ __forceinline__ float2 unpack2(ull a) {
    float lo, hi; asm("mov.b64 {%0, %1}, %2;" : "=f"(lo), "=f"(hi) : "l"(a));
    return make_float2(lo, hi);
}

// =====================================================================
// Kernel A (persistent): weights loaded once; per tile: stage x ->
// fused k+v GEMM -> exp(k)/v to smem -> fine-grained KV/sumK partials.
// 512 threads; tg = tid&63 (2 tokens), og = tid>>6 (head).
// =====================================================================
__global__ void __launch_bounds__(512, 1)
kv_kernel(const float* __restrict__ x,
          const float* __restrict__ Wk, const float* __restrict__ Wv)
{
    extern __shared__ float sm[];
    float* sX  = sm;                    // [96][RS]
    float* sK  = sX + 96 * RS;          // [96][RS]
    float* sV  = sK + 96 * RS;          // [96][RS]
    float* sWk = sV + 96 * RS;          // [96][WS]
    float* sWv = sWk + 96 * WS;         // [96][WS]

    const int tid = threadIdx.x;
    const int tg  = tid & 63;
    const int og  = tid >> 6;
    const int nt  = tg * 2;

    for (int i = tid; i < CCH * CCH; i += 512) {
        int o = i / 96, c = i - o * 96;
        sWk[c * WS + o] = Wk[i];
        sWv[c * WS + o] = Wv[i];
    }

    for (int tile = blockIdx.x; tile < NBLK; tile += GRID) {
        const int b  = tile >> 10;
        const int n0 = (tile & (NTILE - 1)) * TN;

        // stage x tile (float4 coalesced)
        const float* xb = x + (size_t)b * CCH * NTOK + n0;
        for (int i = tid; i < CCH * (TN / 4); i += 512) {
            int c = i >> 5, n4 = i & 31;
            ((float4*)(sX + c * RS))[n4] =
                ((const float4*)(xb + (size_t)c * NTOK))[n4];
        }
        __syncthreads();   // sX ready; also: partials of prev tile done

        // fused k+v GEMM (12+12 accumulators)
        ull ak[12], av[12];
        #pragma unroll
        for (int j = 0; j < 12; j++) { ak[j] = 0ull; av[j] = 0ull; }
        #pragma unroll 2
        for (int c = 0; c < 96; c++) {
            float2 xv = *(const float2*)(sX + c * RS + nt);
            ull x0 = pack2(xv.x, xv.x), x1 = pack2(xv.y, xv.y);
            const ulonglong2* wk4 = (const ulonglong2*)(sWk + c * WS + og * 12);
            const ulonglong2* wv4 = (const ulonglong2*)(sWv + c * WS + og * 12);
            #pragma unroll
            for (int jj = 0; jj < 3; jj++) {
                ulonglong2 wk = wk4[jj], wv = wv4[jj];
                fma2(ak[jj * 4 + 0], wk.x, x0); fma2(ak[jj * 4 + 1], wk.x, x1);
                fma2(ak[jj * 4 + 2], wk.y, x0); fma2(ak[jj * 4 + 3], wk.y, x1);
                fma2(av[jj * 4 + 0], wv.x, x0); fma2(av[jj * 4 + 1], wv.x, x1);
                fma2(av[jj * 4 + 2], wv.y, x0); fma2(av[jj * 4 + 3], wv.y, x1);
            }
        }

        // write exp(k) -> sK, v -> sV
        #pragma unroll
        for (int jj = 0; jj < 3; jj++)
            #pragma unroll
            for (int s = 0; s < 2; s++) {
                float2 k0 = unpack2(ak[jj * 4 + s * 2 + 0]);
                float2 k1 = unpack2(ak[jj * 4 + s * 2 + 1]);
                float2 v0 = unpack2(av[jj * 4 + s * 2 + 0]);
                float2 v1 = unpack2(av[jj * 4 + s * 2 + 1]);
                int o = og * 12 + jj * 4 + s * 2;
                *(float2*)(sK + o * RS + nt)       = make_float2(__expf(k0.x), __expf(k1.x));
                *(float2*)(sK + (o + 1) * RS + nt) = make_float2(__expf(k0.y), __expf(k1.y));
                *(float2*)(sV + o * RS + nt)       = make_float2(v0.x, v1.x);
                *(float2*)(sV + (o + 1) * RS + nt) = make_float2(v0.y, v1.y);
            }
        __syncthreads();   // sK/sV complete

        // fine-grained partials: 288 KV tasks (4x4 ch-block x 32-tok chunk)
        // + 96 sumK tasks (4 ch x 32-tok chunk)
        if (tid < 288) {
            int chunk = tid & 3, bidx = tid >> 2;         // bidx 0..71
            int h = bidx / 9, r = bidx - h * 9, db = r / 3, eb = r - db * 3;
            const float4* pk0 = (const float4*)(sK + (h * 12 + db * 4) * RS) + chunk * 8;
            const float4* pv0 = (const float4*)(sV + (h * 12 + eb * 4) * RS) + chunk * 8;
            ull a2[16];
            #pragma unroll
            for (int i = 0; i < 16; i++) a2[i] = 0ull;
            #pragma unroll
            for (int t = 0; t < 8; t++) {
                float4 K[4], V[4];
                #pragma unroll
                for (int i = 0; i < 4; i++) { K[i] = pk0[i * R4S + t]; V[i] = pv0[i * R4S + t]; }
                ull Kxy[4], Kzw[4], Vxy[4], Vzw[4];
                #pragma unroll
                for (int i = 0; i < 4; i++) {
                    Kxy[i] = pack2(K[i].x, K[i].y); Kzw[i] = pack2(K[i].z, K[i].w);
                    Vxy[i] = pack2(V[i].x, V[i].y); Vzw[i] = pack2(V[i].z, V[i].w);
                }
                #pragma unroll
                for (int i = 0; i < 4; i++)
                    #pragma unroll
                    for (int j = 0; j < 4; j++) {
                        fma2(a2[i * 4 + j], Kxy[i], Vxy[j]);
                        fma2(a2[i * 4 + j], Kzw[i], Vzw[j]);
                    }
            }
            float* po = g_partial + ((size_t)tile * NCHUNK + chunk) * NPART;
            #pragma unroll
            for (int i = 0; i < 4; i++)
                #pragma unroll
                for (int j = 0; j < 4; j++) {
                    float2 v = unpack2(a2[i * 4 + j]);
                    po[h * 144 + (db * 4 + i) * 12 + eb * 4 + j] = v.x + v.y;
                }
        } else if (tid < 384) {
            int s = tid - 288;
            int chunk = s & 3, ci = s >> 2;               // ci 0..23
            float a[4] = {0.f, 0.f, 0.f, 0.f};
            #pragma unroll
            for (int t = 0; t < 8; t++)
                #pragma unroll
                for (int i = 0; i < 4; i++) {
                    float4 K = ((const float4*)(sK + (ci * 4 + i) * RS))[chunk * 8 + t];
                    a[i] += K.x + K.y + K.z + K.w;
                }
            float* po = g_partial + ((size_t)tile * NCHUNK + chunk) * NPART;
            #pragma unroll
            for (int i = 0; i < 4; i++) po[1152 + ci * 4 + i] = a[i];
        }
        // next-loop stage barrier orders partial reads vs sK/sV rewrite
    }
}

// ===== stage-1 reduce: 32 segments of 128 chunk-rows each =====
__global__ void red1_kernel()
{
    int idx = blockIdx.x * 256 + threadIdx.x;
    int b = blockIdx.y, seg = blockIdx.z;
    if (idx >= NPART) return;
    float a = 0.f;
    const float* p = g_partial +
        ((size_t)b * NTILE * NCHUNK + (size_t)seg * (NTILE * NCHUNK / NSEG)) * NPART + idx;
    #pragma unroll 8
    for (int t = 0; t < NTILE * NCHUNK / NSEG; t++) a += p[(size_t)t * NPART];
    g_red1[(seg * BB + b) * NPART + idx] = a;
}

// ===== stage-2 reduce: sum the 32 segments (fixed order) =====
__global__ void red2_kernel()
{
    int gid = blockIdx.x * 256 + threadIdx.x;
    if (gid >= BB * NPART) return;
    int b = gid / NPART, idx = gid - b * NPART;
    float a = 0.f;
    #pragma unroll
    for (int s = 0; s < NSEG; s++) a += g_red1[(s * BB + b) * NPART + idx];
    g_red[gid] = a;
}

// ===== context[b,h,d,e] = KV[h,d,e] / sumK[h*12+d] =====
__global__ void ctx_kernel()
{
    int gid = blockIdx.x * 256 + threadIdx.x;
    if (gid >= BB * 1152) return;
    int b = gid / 1152;
    int r = gid - b * 1152;
    int h = r / 144, d = (r % 144) / 12;
    g_ctx[gid] = g_red[b * NPART + r] / g_red[b * NPART + 1152 + h * 12 + d];
}

// =====================================================================
// Kernel C (persistent): Wq+Wproj+ctx loaded once; per tile: stage x ->
// q GEMM -> softmax+attn in-place -> proj GEMM -> out. 512 threads.
// =====================================================================
__global__ void __launch_bounds__(512, 1)
out2_kernel(const float* __restrict__ x, const float* __restrict__ Wq,
            const float* __restrict__ Wproj, float* __restrict__ out)
{
    extern __shared__ float sm[];
    float* sX   = sm;                   // [96][RS]: x, then attn in-place
    float* sWq  = sX + 96 * RS;         // [96][WS]
    float* sWp  = sWq + 96 * WS;        // [96][WS]
    float* sCtx = sWp + 96 * WS;        // 2*1152 (both batches)

    const int tid = threadIdx.x;
    const int tg  = tid & 63;
    const int og  = tid >> 6;
    const int nt  = tg * 2;

    for (int i = tid; i < CCH * CCH; i += 512) {
        int o = i / 96, c = i - o * 96;
        sWq[c * WS + o] = Wq[i];
        sWp[c * WS + o] = Wproj[i];
    }
    for (int i = tid; i < BB * 1152; i += 512) sCtx[i] = g_ctx[i];

    for (int tile = blockIdx.x; tile < NBLK; tile += GRID) {
        const int b  = tile >> 10;
        const int n0 = (tile & (NTILE - 1)) * TN;

        // stage x tile
        const float* xb = x + (size_t)b * CCH * NTOK + n0;
        for (int i = tid; i < CCH * (TN / 4); i += 512) {
            int c = i >> 5, n4 = i & 31;
            ((float4*)(sX + c * RS))[n4] =
                ((const float4*)(xb + (size_t)c * NTOK))[n4];
        }
        __syncthreads();   // sX staged (and prev-tile proj reads done)

        // q GEMM (12 accumulators)
        ull aq[12];
        #pragma unroll
        for (int j = 0; j < 12; j++) aq[j] = 0ull;
        #pragma unroll 2
        for (int c = 0; c < 96; c++) {
            float2 xv = *(const float2*)(sX + c * RS + nt);
            ull x0 = pack2(xv.x, xv.x), x1 = pack2(xv.y, xv.y);
            const ulonglong2* w4 = (const ulonglong2*)(sWq + c * WS + og * 12);
            #pragma unroll
            for (int jj = 0; jj < 3; jj++) {
                ulonglong2 w = w4[jj];
                fma2(aq[jj * 4 + 0], w.x, x0); fma2(aq[jj * 4 + 1], w.x, x1);
                fma2(aq[jj * 4 + 2], w.y, x0); fma2(aq[jj * 4 + 3], w.y, x1);
            }
        }
        __syncthreads();   // everyone done reading x from sX

        // softmax + attn per token, write into sX in-place
        const ull* cx2 = (const ull*)(sCtx + b * 1152 + og * 144);
        #pragma unroll
        for (int t = 0; t < 2; t++) {
            float qv[12];
            #pragma unroll
            for (int jj = 0; jj < 3; jj++)
                #pragma unroll
                for (int s = 0; s < 2; s++) {
                    float2 v = unpack2(aq[jj * 4 + s * 2 + t]);
                    qv[jj * 4 + s * 2]     = v.x;
                    qv[jj * 4 + s * 2 + 1] = v.y;
                }
            float m = qv[0];
            #pragma unroll
            for (int i = 1; i < 12; i++) m = fmaxf(m, qv[i]);
            float p[12]; float sum = 0.f;
            #pragma unroll
            for (int i = 0; i < 12; i++) { p[i] = __expf(qv[i] - m); sum += p[i]; }
            float inv = 1.f / sum;
            ull at[6];
            #pragma unroll
            for (int j = 0; j < 6; j++) at[j] = 0ull;
            #pragma unroll
            for (int d = 0; d < 12; d++) {
                ull pd = pack2(p[d], p[d]);
                #pragma unroll
                for (int j = 0; j < 6; j++) fma2(at[j], cx2[d * 6 + j], pd);
            }
            #pragma unroll
            for (int j = 0; j < 6; j++) {
                float2 v = unpack2(at[j]);
                sX[(og * 12 + 2 * j) * RS + nt + t]     = v.x * inv;
                sX[(og * 12 + 2 * j + 1) * RS + nt + t] = v.y * inv;
            }
        }
        __syncthreads();   // attn tile complete

        // proj GEMM
        ull ap[12];
        #pragma unroll
        for (int j = 0; j < 12; j++) ap[j] = 0ull;
        #pragma unroll 2
        for (int c = 0; c < 96; c++) {
            float2 av = *(const float2*)(sX + c * RS + nt);
            ull x0 = pack2(av.x, av.x), x1 = pack2(av.y, av.y);
            const ulonglong2* w4 = (const ulonglong2*)(sWp + c * WS + og * 12);
            #pragma unroll
            for (int jj = 0; jj < 3; jj++) {
                ulonglong2 w = w4[jj];
                fma2(ap[jj * 4 + 0], w.x, x0); fma2(ap[jj * 4 + 1], w.x, x1);
                fma2(ap[jj * 4 + 2], w.y, x0); fma2(ap[jj * 4 + 3], w.y, x1);
            }
        }

        float* ob = out + (size_t)b * CCH * NTOK + n0 + nt;
        #pragma unroll
        for (int jj = 0; jj < 3; jj++)
            #pragma unroll
            for (int s = 0; s < 2; s++) {
                float2 a0 = unpack2(ap[jj * 4 + s * 2 + 0]);   // token nt
                float2 a1 = unpack2(ap[jj * 4 + s * 2 + 1]);   // token nt+1
                int o = og * 12 + jj * 4 + s * 2;
                *(float2*)(ob + (size_t)o * NTOK)       = make_float2(a0.x, a1.x);
                *(float2*)(ob + (size_t)(o + 1) * NTOK) = make_float2(a0.y, a1.y);
            }
        __syncthreads();   // proj reads of sX done before next stage
    }
}

extern "C" void kernel_launch(void* const* d_in, const int* in_sizes, int n_in,
                              void* d_out, int out_size)
{
    const float* x  = (const float*)d_in[0];
    const float* Wq = (const float*)d_in[1];
    const float* Wk = (const float*)d_in[2];
    const float* Wv = (const float*)d_in[3];
    const float* Wp = (const float*)d_in[4];
    float* out = (float*)d_out;

    const size_t smA = (size_t)(3 * 96 * RS + 2 * 96 * WS) * sizeof(float);        // 228,864 B
    const size_t smC = (size_t)(96 * RS + 2 * 96 * WS + BB * 1152) * sizeof(float);// 136,704 B
    cudaFuncSetAttribute(kv_kernel,   cudaFuncAttributeMaxDynamicSharedMemorySize, (int)smA);
    cudaFuncSetAttribute(out2_kernel, cudaFuncAttributeMaxDynamicSharedMemorySize, (int)smC);

    kv_kernel<<<GRID, 512, smA>>>(x, Wk, Wv);
    red1_kernel<<<dim3(5, BB, NSEG), 256>>>();
    red2_kernel<<<(BB * NPART + 255) / 256, 256>>>();
    ctx_kernel<<<(BB * 1152 + 255) / 256, 256>>>();
    out2_kernel<<<GRID, 512, smC>>>(x, Wq, Wp, out);
}